// round 10
// baseline (speedup 1.0000x reference)
#include <cuda_runtime.h>

#define NQ   6
#define DIM  64
#define TT   512
#define BB   128

// Fixed per-direction unitaries: U[dir][row][col], built by setup_kernel.
__device__ float2 U_g[2][DIM][DIM];

__device__ __forceinline__ float2 cmul(float2 a, float2 b) {
    return make_float2(a.x * b.x - a.y * b.y, a.x * b.y + a.y * b.x);
}
__device__ __forceinline__ float2 cadd(float2 a, float2 b) {
    return make_float2(a.x + b.x, a.y + b.y);
}

// ---------------------------------------------------------------------------
// Setup: build U = V(params) * Q(poly) as a 64x64 complex matrix per direction.
// ---------------------------------------------------------------------------
__global__ void setup_kernel(const float* __restrict__ poly,
                             const float* __restrict__ fwd_params,
                             const float* __restrict__ bwd_params)
{
    __shared__ float2 M[DIM][DIM];
    const int dir = blockIdx.x;
    const float* params = dir ? bwd_params : fwd_params;
    const int tid = threadIdx.x;  // 0..63

    for (int j = 0; j < DIM; ++j)
        M[tid][j] = make_float2(tid == j ? 1.f : 0.f, 0.f);
    __syncthreads();

    // QSVT block: 4 x (diagonal phase, then CNOT ring)
    for (int d = 0; d <= 3; ++d) {
        float theta = poly[d] * 3.14159265358979323846f;
        float sign  = (float)NQ - 2.0f * (float)__popc(tid);
        float ang   = -0.5f * theta * sign;
        float2 ph;
        sincosf(ang, &ph.y, &ph.x);
        for (int j = 0; j < DIM; ++j)
            M[tid][j] = cmul(ph, M[tid][j]);
        __syncthreads();
        for (int cw = 0; cw < NQ; ++cw) {
            int c  = (cw < NQ - 1) ? cw : NQ - 1;
            int t  = (cw < NQ - 1) ? cw + 1 : 0;
            int mc = 1 << (NQ - 1 - c), mt = 1 << (NQ - 1 - t);
            for (int i = 0; i < DIM; ++i) {
                if ((i & mc) && !(i & mt)) {
                    float2 a = M[i][tid];
                    M[i][tid]      = M[i | mt][tid];
                    M[i | mt][tid] = a;
                }
            }
            __syncthreads();
        }
    }

    // Variational layers
    int idx = 0;
    for (int layer = 0; layer < 2; ++layer) {
        for (int w = 0; w < NQ; ++w) {
            float al = params[idx], be = params[idx + 1], ga = params[idx + 2];
            idx += 3;
            float ca, sa, cb, sb, cg, sg;
            sincosf(0.5f * al, &sa, &ca);
            sincosf(0.5f * be, &sb, &cb);
            sincosf(0.5f * ga, &sg, &cg);
            float2 X00 = make_float2(ca, 0.f),  X01 = make_float2(0.f, -sa);
            float2 X10 = make_float2(0.f, -sa), X11 = make_float2(ca, 0.f);
            float2 Y00 = make_float2(cb, 0.f),  Y01 = make_float2(-sb, 0.f);
            float2 Y10 = make_float2(sb, 0.f),  Y11 = make_float2(cb, 0.f);
            float2 A00 = cadd(cmul(Y00, X00), cmul(Y01, X10));
            float2 A01 = cadd(cmul(Y00, X01), cmul(Y01, X11));
            float2 A10 = cadd(cmul(Y10, X00), cmul(Y11, X10));
            float2 A11 = cadd(cmul(Y10, X01), cmul(Y11, X11));
            float2 Z0 = make_float2(cg, -sg), Z1 = make_float2(cg, sg);
            float2 u00 = cmul(Z0, A00), u01 = cmul(Z0, A01);
            float2 u10 = cmul(Z1, A10), u11 = cmul(Z1, A11);
            int m = 1 << (NQ - 1 - w);
            for (int i0 = 0; i0 < DIM; ++i0) {
                if (i0 & m) continue;
                float2 a = M[i0][tid], b = M[i0 | m][tid];
                M[i0][tid]     = cadd(cmul(u00, a), cmul(u01, b));
                M[i0 | m][tid] = cadd(cmul(u10, a), cmul(u11, b));
            }
            __syncthreads();
        }
        for (int c = 0; c < NQ - 1; ++c) {
            int t  = c + 1;
            int mc = 1 << (NQ - 1 - c), mt = 1 << (NQ - 1 - t);
            for (int i = 0; i < DIM; ++i) {
                if ((i & mc) && !(i & mt)) {
                    float2 a = M[i][tid];
                    M[i][tid]      = M[i | mt][tid];
                    M[i | mt][tid] = a;
                }
            }
            __syncthreads();
        }
    }

    for (int j = 0; j < DIM; ++j)
        U_g[dir][tid][j] = M[tid][j];
}

// ---------------------------------------------------------------------------
// Main scan. z_w = cos(x_w)*<Z_w> - sin(x_w)*<X_w> on psi1 = U*psi0 (no RY
// butterflies). <Z_w> via WHT of |psi1|^2, <X_w> via partner products; both
// reduced in ONE 6-level tree over 7 values.
// ---------------------------------------------------------------------------
__global__ void __launch_bounds__(64)
hydra_kernel(const float* __restrict__ angles,
             const float* __restrict__ fwd_coeff,
             const float* __restrict__ bwd_coeff,
             float* __restrict__ out)
{
    const int cta  = blockIdx.x;
    const int dir  = cta >> 7;
    const int b    = cta & 127;
    const int tid  = threadIdx.x;
    const int lane = tid & 31;
    const int warp = tid >> 5;

    // U row in registers
    float2 Urow[DIM];
#pragma unroll
    for (int j = 0; j < DIM; ++j)
        Urow[j] = U_g[dir][tid][j];

    __shared__ float2 xt[TT * NQ];   // (cos x, sin x) per (t, w)
    __shared__ float2 hcs[NQ];       // (cos h/2, sin h/2)
    __shared__ float4 p0v[DIM / 4];  // psi0 (real)
    __shared__ float  ex[2 * DIM];   // re/im cross-warp exchange
    __shared__ float2 fin[2][NQ];    // (P_wht, Q_sum) per warp per wire

    // one-time: cos/sin table for all steps (full angle x)
    for (int idx = tid; idx < TT * NQ; idx += 64) {
        float a = angles[(size_t)b * (TT * NQ) + idx];
        float s, c; sincosf(a, &s, &c);
        xt[idx] = make_float2(c, s);
    }
    if (tid < NQ) hcs[tid] = make_float2(1.f, 0.f);   // h = 0

    float cf    = dir ? bwd_coeff[0] : fwd_coeff[0];
    float coeff = 1.0f / (1.0f + expf(-cf));

    const unsigned FULL = 0xFFFFFFFFu;
    // designated lanes in each warp: 0 (wire 0) and 16,8,4,2,1 (wires 1..5)
    const bool desig = (lane == 0) || (__popc(lane) == 1 && lane <= 16);
    const int  wire  = (lane == 0) ? 0 : (5 - (31 - __clz(lane | 1)));

    __syncthreads();

    for (int step = 0; step < TT; ++step) {
        const int t = dir ? (TT - 1 - step) : step;

        // psi0[tid] = prod_w (bit_w ? sin : cos)(h_w/2)
        float v = 1.f;
#pragma unroll
        for (int w = 0; w < NQ; ++w) {
            float2 cs = hcs[w];
            v *= ((tid >> (NQ - 1 - w)) & 1) ? cs.y : cs.x;
        }
        ((float*)p0v)[tid] = v;
        __syncthreads();                               // #1: p0 ready

        // psi1[tid] = Urow . p0   (complex row . real vec)
        float re0 = 0.f, re1 = 0.f, re2 = 0.f, re3 = 0.f;
        float im0 = 0.f, im1 = 0.f, im2 = 0.f, im3 = 0.f;
#pragma unroll
        for (int jj = 0; jj < DIM / 4; ++jj) {
            float4 pv = p0v[jj];
            int j = jj * 4;
            re0 = fmaf(Urow[j    ].x, pv.x, re0); im0 = fmaf(Urow[j    ].y, pv.x, im0);
            re1 = fmaf(Urow[j + 1].x, pv.y, re1); im1 = fmaf(Urow[j + 1].y, pv.y, im1);
            re2 = fmaf(Urow[j + 2].x, pv.z, re2); im2 = fmaf(Urow[j + 2].y, pv.z, im2);
            re3 = fmaf(Urow[j + 3].x, pv.w, re3); im3 = fmaf(Urow[j + 3].y, pv.w, im3);
        }
        float re = (re0 + re1) + (re2 + re3);
        float im = (im0 + im1) + (im2 + im3);

        ex[tid] = re; ex[DIM + tid] = im;
        __syncthreads();                               // #2: cross-warp partners

        float rp = ex[tid ^ 32], ip = ex[DIM + (tid ^ 32)];
        float p  = re * re + im * im;                  // |psi1_i|^2
        float q0 = re * rp + im * ip;                  // wire 0 (bit 5) partner
        float q1 = re * __shfl_xor_sync(FULL, re, 16) + im * __shfl_xor_sync(FULL, im, 16);
        float q2 = re * __shfl_xor_sync(FULL, re,  8) + im * __shfl_xor_sync(FULL, im,  8);
        float q3 = re * __shfl_xor_sync(FULL, re,  4) + im * __shfl_xor_sync(FULL, im,  4);
        float q4 = re * __shfl_xor_sync(FULL, re,  2) + im * __shfl_xor_sync(FULL, im,  2);
        float q5 = re * __shfl_xor_sync(FULL, re,  1) + im * __shfl_xor_sync(FULL, im,  1);

        // one combined 5-level in-warp tree: WHT on p, plain sums on q0..q5
#pragma unroll
        for (int m = 1; m <= 16; m <<= 1) {
            float pp = __shfl_xor_sync(FULL, p, m);
            p = (lane & m) ? (pp - p) : (p + pp);
            q0 += __shfl_xor_sync(FULL, q0, m);
            q1 += __shfl_xor_sync(FULL, q1, m);
            q2 += __shfl_xor_sync(FULL, q2, m);
            q3 += __shfl_xor_sync(FULL, q3, m);
            q4 += __shfl_xor_sync(FULL, q4, m);
            q5 += __shfl_xor_sync(FULL, q5, m);
        }
        if (desig) {
            float q = (wire == 0) ? q0 : (wire == 1) ? q1 : (wire == 2) ? q2
                    : (wire == 3) ? q3 : (wire == 4) ? q4 : q5;
            fin[warp][wire] = make_float2(p, q);
        }
        __syncthreads();                               // #3: per-warp partials

        if (desig && warp == 0) {
            float2 f0 = fin[0][wire], f1 = fin[1][wire];
            float Z = (wire == 0) ? (f0.x - f1.x) : (f0.x + f1.x);   // <Z_w>
            float X = f0.y + f1.y;                                   // <X_w>
            float2 cs = xt[t * NQ + wire];
            float z = cs.x * Z - cs.y * X;
            atomicAdd(&out[((size_t)b * TT + t) * NQ + wire], coeff * z);
            float sh, ch; sincosf(0.5f * z, &sh, &ch);
            hcs[wire] = make_float2(ch, sh);
        }
        __syncthreads();                               // #4: hcs ready
    }
}

__global__ void zero_kernel(float* __restrict__ out, int n)
{
    int i = blockIdx.x * blockDim.x + threadIdx.x;
    if (i < n) out[i] = 0.f;
}

extern "C" void kernel_launch(void* const* d_in, const int* in_sizes, int n_in,
                              void* d_out, int out_size)
{
    const float* angles = (const float*)d_in[0];
    const float* poly   = (const float*)d_in[1];
    const float* fwdp   = (const float*)d_in[2];
    const float* bwdp   = (const float*)d_in[3];
    const float* fwdc   = (const float*)d_in[4];
    const float* bwdc   = (const float*)d_in[5];
    float* out = (float*)d_out;

    zero_kernel<<<(out_size + 255) / 256, 256>>>(out, out_size);
    setup_kernel<<<2, 64>>>(poly, fwdp, bwdp);
    hydra_kernel<<<2 * BB, 64>>>(angles, fwdc, bwdc, out);
}